// round 9
// baseline (speedup 1.0000x reference)
#include <cuda_runtime.h>
#include <math.h>
#include <stdint.h>

#define THREADS 256

// ---------------- layer tables ----------------
__constant__ int c_H[5]        = {480, 240, 120, 60, 30};
__constant__ int c_chanBase[5] = {0, 64, 192, 448, 960};
__constant__ int c_procBase[5] = {0, 230400, 288000, 302400, 306000};

// ---------------- scratch (device globals; no allocation) ----------------
__device__ unsigned g_cmax[1472];        // raw bits of per-channel max (values >= 0)
__device__ int      g_hist[1472][12];    // [0:6) histc bins, [6:12) gidx bins (j<5 + border)
__device__ float    g_lut[1472][6];      // per-channel contribution LUT
__device__ float    g_S5[5];             // sum_c lut_c[5] per layer
__device__ float    g_bord[5];           // border proc value per layer
__device__ unsigned g_rarecnt;
__device__ unsigned g_rare[28108800];    // packed rare records: pix|ch<<18|b2<<29
__device__ float    g_proc[306900];      // per-layer proc maps (raw, pre-threshold)
__device__ unsigned g_pstat[5][2];       // proc min/max per layer (encoded)
__device__ float    g_group[5][57600];   // resized+thresholded maps
__device__ unsigned g_gstat[5][2];       // group min/max per layer (encoded)

// ---------------- float <-> orderable uint ----------------
__device__ __forceinline__ unsigned fenc(float f) {
    unsigned b = __float_as_uint(f);
    return (b & 0x80000000u) ? ~b : (b | 0x80000000u);
}
__device__ __forceinline__ float fdec(unsigned u) {
    unsigned b = (u & 0x80000000u) ? (u & 0x7FFFFFFFu) : ~u;
    return __uint_as_float(b);
}

__device__ __forceinline__ void blockMinMax(float vmn, float vmx, unsigned* stat, float* s) {
#pragma unroll
    for (int o = 16; o; o >>= 1) {
        vmn = fminf(vmn, __shfl_xor_sync(0xFFFFFFFFu, vmn, o));
        vmx = fmaxf(vmx, __shfl_xor_sync(0xFFFFFFFFu, vmx, o));
    }
    int w = threadIdx.x >> 5;
    if ((threadIdx.x & 31) == 0) { s[w] = vmn; s[8 + w] = vmx; }
    __syncthreads();
    if (threadIdx.x == 0) {
        float a = s[0], b = s[8];
#pragma unroll
        for (int i = 1; i < 8; i++) { a = fminf(a, s[i]); b = fmaxf(b, s[8 + i]); }
        atomicMin(&stat[0], fenc(a));
        atomicMax(&stat[1], fenc(b));
    }
    __syncthreads();
}

// ---------------- pass 0: init ----------------
__global__ void __launch_bounds__(THREADS) k_init() {
    int i = blockIdx.x * THREADS + threadIdx.x;
    if (i < 1472 * 12) ((int*)g_hist)[i] = 0;
    if (i < 1472) g_cmax[i] = 0u;
    if (i == 0) g_rarecnt = 0u;
    if (i < 5) {
        g_pstat[i][0] = 0xFFFFFFFFu; g_pstat[i][1] = 0u;
        g_gstat[i][0] = 0xFFFFFFFFu; g_gstat[i][1] = 0u;
    }
}

// ---------------- block decode for passes A/B ----------------
// tiles per channel: {16,4,1,1,1}; blocks per layer {1024,512,256,512,512}; total 2816
struct BlkInfo { int layer, cloc, tile; };
__device__ __forceinline__ BlkInfo decodeAB(int b) {
    BlkInfo r;
    if (b < 1024)      { r.layer = 0; r.cloc = b >> 4;            r.tile = b & 15; }
    else if (b < 1536) { int t = b - 1024; r.layer = 1; r.cloc = t >> 2; r.tile = t & 3; }
    else if (b < 1792) { r.layer = 2; r.cloc = b - 1536; r.tile = 0; }
    else if (b < 2304) { r.layer = 3; r.cloc = b - 1792; r.tile = 0; }
    else               { r.layer = 4; r.cloc = b - 2304; r.tile = 0; }
    return r;
}

// ---------------- pass A: per-channel interior MAX (min is exactly 0) ----------------
template <int H, int T>
__device__ __forceinline__ float mxv_body(const float* __restrict__ base, int tile) {
    constexpr int W = H, F4 = W / 4;
    int rowsThis = (H - 2 - tile + T - 1) / T;
    int total = rowsThis * F4;
    float mx = 0.f;
    for (int i = threadIdx.x; i < total; i += THREADS) {
        int m = i / F4, j = i - m * F4;
        int r = 1 + tile + m * T;
        float4 v = *(const float4*)(base + r * W + 4 * j);
        if (j == 0) v.x = 0.f;
        if (j == F4 - 1) v.w = 0.f;
        mx = fmaxf(mx, fmaxf(fmaxf(v.x, v.y), fmaxf(v.z, v.w)));
    }
    return mx;
}
template <int H>
__device__ __forceinline__ float mxs_body(const float* __restrict__ base) {
    constexpr int W = H, IW = W - 2, NI = IW * (H - 2);
    float mx = 0.f;
    for (int i = threadIdx.x; i < NI; i += THREADS) {
        int q = i / IW, col = i - q * IW;
        mx = fmaxf(mx, base[(q + 1) * W + col + 1]);
    }
    return mx;
}

__global__ void __launch_bounds__(THREADS) k_max(const float* __restrict__ p0, const float* __restrict__ p1,
                                                 const float* __restrict__ p2, const float* __restrict__ p3,
                                                 const float* __restrict__ p4, int off) {
    __shared__ float sred[8];
    BlkInfo bi = decodeAB(blockIdx.x + off);
    float mx; int ch;
    switch (bi.layer) {
        case 0: ch = bi.cloc;       mx = mxv_body<480, 16>(p0 + (long long)bi.cloc * 230400, bi.tile); break;
        case 1: ch = 64 + bi.cloc;  mx = mxv_body<240, 4>(p1 + (long long)bi.cloc * 57600, bi.tile); break;
        case 2: ch = 192 + bi.cloc; mx = mxv_body<120, 1>(p2 + (long long)bi.cloc * 14400, bi.tile); break;
        case 3: ch = 448 + bi.cloc; mx = mxv_body<60, 1>(p3 + (long long)bi.cloc * 3600, bi.tile); break;
        default: ch = 960 + bi.cloc; mx = mxs_body<30>(p4 + (long long)bi.cloc * 900); break;
    }
#pragma unroll
    for (int o = 16; o; o >>= 1) mx = fmaxf(mx, __shfl_xor_sync(0xFFFFFFFFu, mx, o));
    if ((threadIdx.x & 31) == 0) sred[threadIdx.x >> 5] = mx;
    __syncthreads();
    if (threadIdx.x == 0) {
        float a = sred[0];
#pragma unroll
        for (int i = 1; i < 8; i++) a = fmaxf(a, sred[i]);
        atomicMax(&g_cmax[ch], __float_as_uint(a));   // nonneg floats: raw-bit monotonic
    }
}

// ---------------- pass B: histc hist + rare-pixel emission ----------------
// i1 = floor(v * 1536/mx); b1 = min(i1>>8,5) (histc bin); rare iff i1<6 (gidx<5)
__device__ __forceinline__ void hist_flush1(unsigned long long h1, int ch) {
#pragma unroll
    for (int j = 0; j < 6; j++) {
        int c1 = (int)((h1 >> (j * 10)) & 1023u);
        c1 = __reduce_add_sync(0xFFFFFFFFu, c1);
        if ((threadIdx.x & 31) == 0 && c1) atomicAdd(&g_hist[ch][j], c1);
    }
}

__device__ __forceinline__ void rare_emit(bool rr, unsigned rec, int ch, int b2) {
    unsigned m = __ballot_sync(0xFFFFFFFFu, rr);
    if (m) {
        int ldr = __ffs(m) - 1;
        unsigned base;
        if ((threadIdx.x & 31) == ldr) base = atomicAdd(&g_rarecnt, (unsigned)__popc(m));
        base = __shfl_sync(0xFFFFFFFFu, base, ldr);
        if (rr) {
            unsigned off = base + __popc(m & ((1u << (threadIdx.x & 31)) - 1u));
            g_rare[off] = rec;
            atomicAdd(&g_hist[ch][6 + b2], 1);
        }
    }
}

template <int H, int T>
__device__ void histv_body(const float* __restrict__ base, int tile, int ch) {
    constexpr int W = H, F4 = W / 4;
    float mx = __uint_as_float(g_cmax[ch]);
    float s = (mx > 0.f) ? __fdiv_rn(1536.f, mx) : 0.f;
    unsigned long long h1 = 0ULL;
    int rowsThis = (H - 2 - tile + T - 1) / T;
    int total = rowsThis * F4;
    int iters = (total + THREADS - 1) / THREADS;
    for (int it = 0; it < iters; it++) {
        int i = it * THREADS + threadIdx.x;
        bool ok = i < total;
        int ii = ok ? i : 0;
        int m = ii / F4, j = ii - m * F4;
        int r = 1 + tile + m * T;
        float4 v = ok ? *(const float4*)(base + r * W + 4 * j)
                      : make_float4(0.f, 0.f, 0.f, 0.f);
        if (j == 0) v.x = 0.f;
        if (j == F4 - 1) v.w = 0.f;
        int i1[4];
        i1[0] = __float2int_rd(__fmul_rn(v.x, s));
        i1[1] = __float2int_rd(__fmul_rn(v.y, s));
        i1[2] = __float2int_rd(__fmul_rn(v.z, s));
        i1[3] = __float2int_rd(__fmul_rn(v.w, s));
        if (ok) {
#pragma unroll
            for (int k = 0; k < 4; k++) h1 += 1ULL << (min(i1[k] >> 8, 5) * 10);
        }
        unsigned pix = (unsigned)(r * W + 4 * j);
#pragma unroll
        for (int k = 0; k < 4; k++) {
            bool rr = ok && (i1[k] < 6);
            if (k == 0) rr = rr && (j != 0);          // border col 0 handled analytically
            if (k == 3) rr = rr && (j != F4 - 1);     // border col W-1
            int b2 = max(i1[k] - 1, 0);               // <= 4 whenever rr
            rare_emit(rr, (pix + k) | ((unsigned)ch << 18) | ((unsigned)b2 << 29), ch, b2);
        }
    }
    hist_flush1(h1, ch);
    if (tile == 0 && threadIdx.x == 0) {
        atomicAdd(&g_hist[ch][0], 2 * W);                 // rows 0,H-1 -> histc bin 0
        atomicAdd(&g_hist[ch][6 + 0], 2 * (H + W) - 4);   // full border -> gidx bin 0
    }
}

template <int H>
__device__ void hists_body(const float* __restrict__ base, int ch) {
    constexpr int W = H, IW = W - 2, NI = IW * (H - 2);
    float mx = __uint_as_float(g_cmax[ch]);
    float s = (mx > 0.f) ? __fdiv_rn(1536.f, mx) : 0.f;
    unsigned long long h1 = 0ULL;
    int iters = (NI + THREADS - 1) / THREADS;
    for (int it = 0; it < iters; it++) {
        int i = it * THREADS + threadIdx.x;
        bool ok = i < NI;
        int ii = ok ? i : 0;
        int q = ii / IW, col = ii - q * IW;
        int pix = (q + 1) * W + col + 1;
        float v = ok ? base[pix] : 1e30f;
        int i1 = __float2int_rd(__fmul_rn(v, s));
        if (ok) h1 += 1ULL << (min(i1 >> 8, 5) * 10);
        bool rr = ok && (i1 < 6);
        int b2 = max(i1 - 1, 0);
        rare_emit(rr, (unsigned)pix | ((unsigned)ch << 18) | ((unsigned)b2 << 29), ch, b2);
    }
    hist_flush1(h1, ch);
    if (threadIdx.x == 0) {
        int Nb = 2 * (H + W) - 4;
        atomicAdd(&g_hist[ch][0], Nb);
        atomicAdd(&g_hist[ch][6 + 0], Nb);
    }
}

__global__ void __launch_bounds__(THREADS) k_hist(const float* __restrict__ p0, const float* __restrict__ p1,
                                                  const float* __restrict__ p2, const float* __restrict__ p3,
                                                  const float* __restrict__ p4, int off) {
    BlkInfo bi = decodeAB(blockIdx.x + off);
    switch (bi.layer) {
        case 0: histv_body<480, 16>(p0 + (long long)bi.cloc * 230400, bi.tile, bi.cloc); break;
        case 1: histv_body<240, 4>(p1 + (long long)bi.cloc * 57600, bi.tile, 64 + bi.cloc); break;
        case 2: histv_body<120, 1>(p2 + (long long)bi.cloc * 14400, bi.tile, 192 + bi.cloc); break;
        case 3: histv_body<60, 1>(p3 + (long long)bi.cloc * 3600, bi.tile, 448 + bi.cloc); break;
        default: hists_body<30>(p4 + (long long)bi.cloc * 900, 960 + bi.cloc); break;
    }
}

// ---------------- pass LUT: per-channel 6-entry contribution table ----------------
__global__ void __launch_bounds__(32) k_lut() {
    int ch = blockIdx.x * 32 + threadIdx.x;
    if (ch >= 1472) return;
    int layer = ch < 64 ? 0 : ch < 192 ? 1 : ch < 448 ? 2 : ch < 960 ? 3 : 4;
    int H = c_H[layer], W = H, HW = H * W;
    float Nf = (float)HW;

    int gg[6], sg = 0;
#pragma unroll
    for (int j = 0; j < 5; j++) { gg[j] = g_hist[ch][6 + j]; sg += gg[j]; }
    gg[5] = HW - sg;                          // all non-rare interior pixels have gidx 5

    float hv[6];
#pragma unroll
    for (int j = 0; j < 6; j++)
        hv[j] = -logf(__fdiv_rn((float)g_hist[ch][j], Nf) + 1e-4f);

    float minv = 1e30f, maxv = -1e30f;
#pragma unroll
    for (int j = 0; j < 6; j++)
        if (gg[j] > 0) { minv = fminf(minv, hv[j]); maxv = fmaxf(maxv, hv[j]); }
    float rh = maxv - minv;

    const int jb = 0;                          // border pixels (value 0) -> gidx bin 0
    bool first = (ch == c_chanBase[layer]);    // channel 0 keeps its border in the map

    float lut[6] = {0.f, 0.f, 0.f, 0.f, 0.f, 0.f};
    if (rh > 0.f) {
        float dn[6];
#pragma unroll
        for (int j = 0; j < 6; j++)
            dn[j] = (gg[j] > 0) ? __fdiv_rn(hv[j] - minv, rh) : 0.f;
        float meandn = 0.f;
#pragma unroll
        for (int j = 0; j < 6; j++) meandn += (float)gg[j] * dn[j];
        meandn = __fdiv_rn(meandn, Nf);
        float w1 = 1.f - meandn; w1 *= w1;     // (max_dst - mean_dst)^2, max_dst == 1
        int Nb = 2 * (H + W) - 4;
        float mean_m = 0.f;
        float max_m = first ? -1e30f : 0.f;    // zeroed border contributes 0 for c>=1
#pragma unroll
        for (int j = 0; j < 6; j++) {
            int cnt = gg[j] - ((!first && j == jb) ? Nb : 0);
            float rv = dn[j] * w1;
            if (cnt > 0) { mean_m += (float)cnt * rv; max_m = fmaxf(max_m, rv); }
        }
        mean_m = __fdiv_rn(mean_m, Nf);
        if (max_m > 0.f) {
            float w2 = max_m - mean_m; w2 *= w2;   // min_m == 0 always
#pragma unroll
            for (int j = 0; j < 6; j++)
                lut[j] = __fmul_rn(__fdiv_rn(dn[j] * w1, max_m), w2);
        }
    }
#pragma unroll
    for (int j = 0; j < 6; j++) g_lut[ch][j] = lut[j];
}

// ---------------- pass S5: per-layer sum of lut[5] + border value ----------------
__global__ void __launch_bounds__(THREADS) k_s5() {
    __shared__ float sh[THREADS];
    int l = blockIdx.x;
    int C = (l == 0) ? 64 : (l == 1) ? 128 : (l == 2) ? 256 : 512;
    int cb = c_chanBase[l];
    float s = 0.f;
    for (int c = threadIdx.x; c < C; c += THREADS) s += g_lut[cb + c][5];
    sh[threadIdx.x] = s;
    __syncthreads();
    for (int st = THREADS / 2; st; st >>= 1) {
        if (threadIdx.x < st) sh[threadIdx.x] += sh[threadIdx.x + st];
        __syncthreads();
    }
    if (threadIdx.x == 0) { g_S5[l] = sh[0]; g_bord[l] = g_lut[cb][0]; }
}

// ---------------- pass fill: proc = S5 interior, bord on borders ----------------
__global__ void __launch_bounds__(THREADS) k_fill() {
    int i = blockIdx.x * THREADS + threadIdx.x;
    if (i >= 306900) return;
    int layer = i < 230400 ? 0 : i < 288000 ? 1 : i < 302400 ? 2 : i < 306000 ? 3 : 4;
    int W = c_H[layer];
    int p = i - c_procBase[layer];
    int r = p / W, c = p - r * W;
    bool bd = (r == 0) | (c == 0) | (r == W - 1) | (c == W - 1);
    g_proc[i] = bd ? g_bord[layer] : g_S5[layer];
}

// ---------------- pass scatter: apply rare corrections ----------------
__global__ void __launch_bounds__(THREADS) k_scatter() {
    unsigned n = g_rarecnt;
    for (unsigned i = blockIdx.x * THREADS + threadIdx.x; i < n; i += gridDim.x * THREADS) {
        unsigned e = g_rare[i];
        unsigned pix = e & 0x3FFFFu;
        unsigned ch  = (e >> 18) & 0x7FFu;
        unsigned b2  = e >> 29;
        int layer = ch < 64 ? 0 : ch < 192 ? 1 : ch < 448 ? 2 : ch < 960 ? 3 : 4;
        float d = g_lut[ch][b2] - g_lut[ch][5];
        atomicAdd(&g_proc[c_procBase[layer] + pix], d);
    }
}

// ---------------- pass pstat: per-layer proc min/max ----------------
// blocks: l0:900 l1:225 l2:57 l3:15 l4:4 -> 1201
__global__ void __launch_bounds__(THREADS) k_pstat() {
    __shared__ float sred[16];
    int b = blockIdx.x;
    int layer, loc;
    if (b < 900)       { layer = 0; loc = b; }
    else if (b < 1125) { layer = 1; loc = b - 900; }
    else if (b < 1182) { layer = 2; loc = b - 1125; }
    else if (b < 1197) { layer = 3; loc = b - 1182; }
    else               { layer = 4; loc = b - 1197; }
    int H = c_H[layer], HW = H * H, pb = c_procBase[layer];
    int p = loc * THREADS + threadIdx.x;
    float val = g_proc[pb + ((p < HW) ? p : 0)];
    blockMinMax(val, val, g_pstat[layer], sred);
}

// ---------------- pass E: normalize+threshold (fused) + resize + group min/max ----
__device__ __forceinline__ float fth(float v, float mnp, float rng) {
    float pn = (rng == 0.f) ? 0.f : __fdiv_rn(v - mnp, rng);
    return (pn < 0.2f) ? 0.f : pn;
}

__global__ void __launch_bounds__(THREADS) k_resize() {
    __shared__ float sred[16];
    int b = blockIdx.x;
    int layer = b / 225;
    int p = (b - layer * 225) * THREADS + threadIdx.x;   // < 57600 exactly
    int y = p / 240, x = p % 240;
    float mnp = fdec(g_pstat[layer][0]);
    float mxp = fdec(g_pstat[layer][1]);
    float rng = mxp - mnp;
    float val;
    if (layer == 0) {
        // 480 -> 240 antialiased: taps [1,3,3,1]/8, edge-renormalized
        const float w4[4] = {1.f, 3.f, 3.f, 1.f};
        float wxs = 0.f;
#pragma unroll
        for (int j = 0; j < 4; j++) { int tx = 2 * x - 1 + j; if (tx >= 0 && tx < 480) wxs += w4[j]; }
        float acc = 0.f, wys = 0.f;
#pragma unroll
        for (int a = 0; a < 4; a++) {
            int ty = 2 * y - 1 + a;
            if (ty < 0 || ty > 479) continue;
            wys += w4[a];
            const float* row = g_proc + ty * 480;
            float ra = 0.f;
#pragma unroll
            for (int j = 0; j < 4; j++) {
                int tx = 2 * x - 1 + j;
                if (tx >= 0 && tx < 480) ra += w4[j] * fth(row[tx], mnp, rng);
            }
            acc += w4[a] * ra;
        }
        val = acc / (wys * wxs);
    } else if (layer == 1) {
        val = fth(g_proc[230400 + p], mnp, rng);         // identity resize
    } else {
        int H = layer == 2 ? 120 : layer == 3 ? 60 : 30;
        int base = layer == 2 ? 288000 : layer == 3 ? 302400 : 306000;
        const float* pr = g_proc + base;
        float s = (float)H / 240.f;                      // 0.5 / 0.25 / 0.125 exact
        float cy = (y + 0.5f) * s - 0.5f;
        float cx = (x + 0.5f) * s - 0.5f;
        float fly = floorf(cy), flx = floorf(cx);
        float fy = cy - fly, fx = cx - flx;
        int iy = (int)fly, ix = (int)flx;
        int y0 = max(iy, 0), y1 = min(iy + 1, H - 1);
        int x0 = max(ix, 0), x1 = min(ix + 1, H - 1);
        float a = fth(pr[y0 * H + x0], mnp, rng), bv = fth(pr[y0 * H + x1], mnp, rng);
        float c = fth(pr[y1 * H + x0], mnp, rng), d = fth(pr[y1 * H + x1], mnp, rng);
        val = (1.f - fy) * ((1.f - fx) * a + fx * bv) + fy * ((1.f - fx) * c + fx * d);
    }
    g_group[layer][p] = val;
    blockMinMax(val, val, g_gstat[layer], sred);
}

// ---------------- pass F: group normalize(0,256), write groups + sum ----------------
__global__ void __launch_bounds__(THREADS) k_final(float* __restrict__ out, int out_size) {
    int p = blockIdx.x * THREADS + threadIdx.x;          // 225 blocks * 256 = 57600 exactly
    float s = 0.f;
#pragma unroll
    for (int g = 0; g < 5; g++) {
        float mn = fdec(g_gstat[g][0]);
        float mx = fdec(g_gstat[g][1]);
        float rng = mx - mn;
        float v = g_group[g][p];
        float gv = (rng == 0.f) ? 0.f : __fmul_rn(__fdiv_rn(v - mn, rng), 256.f);
        if (out_size >= 345600) out[57600 + p * 5 + g] = gv;
        s += gv;
    }
    out[p] = s;
}

// ---------------- launch ----------------
extern "C" void kernel_launch(void* const* d_in, const int* in_sizes, int n_in,
                              void* d_out, int out_size) {
    const int want[5] = {14745600, 7372800, 3686400, 1843200, 460800};
    const float* L[5] = {nullptr, nullptr, nullptr, nullptr, nullptr};
    for (int i = 0; i < n_in && i < 16; i++)
        for (int j = 0; j < 5; j++)
            if (in_sizes[i] == want[j] && L[j] == nullptr) { L[j] = (const float*)d_in[i]; break; }
    for (int j = 0; j < 5; j++) if (!L[j] && j < n_in) L[j] = (const float*)d_in[j];

    k_init<<<69, THREADS>>>();
    // L2-resident pairing: each (max, hist) pair works on a <=60 MB group so the
    // hist pass re-reads from L2 instead of DRAM.
    k_max<<<1024, THREADS>>>(L[0], L[1], L[2], L[3], L[4], 0);      // layer 0 (56 MB)
    k_hist<<<1024, THREADS>>>(L[0], L[1], L[2], L[3], L[4], 0);
    k_max<<<1792, THREADS>>>(L[0], L[1], L[2], L[3], L[4], 1024);   // layers 1-4 (56 MB)
    k_hist<<<1792, THREADS>>>(L[0], L[1], L[2], L[3], L[4], 1024);
    k_lut<<<46, 32>>>();
    k_s5<<<5, THREADS>>>();
    k_fill<<<1199, THREADS>>>();
    k_scatter<<<128, THREADS>>>();
    k_pstat<<<1201, THREADS>>>();
    k_resize<<<1125, THREADS>>>();
    k_final<<<225, THREADS>>>((float*)d_out, out_size);
}

// round 10
// speedup vs baseline: 1.0648x; 1.0648x over previous
#include <cuda_runtime.h>
#include <math.h>
#include <stdint.h>

#define THREADS 256
#define FULLM 0xFFFFFFFFu

// ---------------- layer tables ----------------
__constant__ int c_H[5]        = {480, 240, 120, 60, 30};
__constant__ int c_chanBase[5] = {0, 64, 192, 448, 960};
__constant__ int c_C[5]        = {64, 128, 256, 512, 512};
__constant__ int c_procBase[5] = {0, 230400, 288000, 302400, 306000};

// ---------------- scratch (device globals; no allocation) ----------------
__device__ unsigned g_cmax[1472];        // raw bits of per-channel max (values >= 0)
__device__ unsigned g_cnt[1472];         // tiles-arrived counter per channel
__device__ int      g_hist[1472][12];    // [0:6) histc bins, [6:12) gidx bins (j<5 + border)
__device__ float    g_lut[1472][6];      // per-channel contribution LUT
__device__ float    g_S5[5];             // sum_c lut_c[5] per layer
__device__ float    g_bord[5];           // border proc value per layer
__device__ unsigned g_rarecnt;
__device__ unsigned g_rare[28108800];    // packed rare records: pix|ch<<18|b2<<29
__device__ float    g_proc[306900];      // per-layer proc maps (raw, pre-threshold)
__device__ unsigned g_pstat[5][2];       // proc min/max per layer (encoded)
__device__ float    g_group[5][57600];   // resized+thresholded maps
__device__ unsigned g_gstat[5][2];       // group min/max per layer (encoded)

// ---------------- float <-> orderable uint ----------------
__device__ __forceinline__ unsigned fenc(float f) {
    unsigned b = __float_as_uint(f);
    return (b & 0x80000000u) ? ~b : (b | 0x80000000u);
}
__device__ __forceinline__ float fdec(unsigned u) {
    unsigned b = (u & 0x80000000u) ? (u & 0x7FFFFFFFu) : ~u;
    return __uint_as_float(b);
}

__device__ __forceinline__ void blockMinMax(float vmn, float vmx, unsigned* stat, float* s) {
#pragma unroll
    for (int o = 16; o; o >>= 1) {
        vmn = fminf(vmn, __shfl_xor_sync(FULLM, vmn, o));
        vmx = fmaxf(vmx, __shfl_xor_sync(FULLM, vmx, o));
    }
    int w = threadIdx.x >> 5;
    if ((threadIdx.x & 31) == 0) { s[w] = vmn; s[8 + w] = vmx; }
    __syncthreads();
    if (threadIdx.x == 0) {
        float a = s[0], b = s[8];
#pragma unroll
        for (int i = 1; i < 8; i++) { a = fminf(a, s[i]); b = fmaxf(b, s[8 + i]); }
        atomicMin(&stat[0], fenc(a));
        atomicMax(&stat[1], fenc(b));
    }
    __syncthreads();
}

// ---------------- pass 0: init ----------------
__global__ void __launch_bounds__(THREADS) k_init() {
    int i = blockIdx.x * THREADS + threadIdx.x;
    if (i < 1472 * 12) ((int*)g_hist)[i] = 0;
    if (i < 1472) { g_cmax[i] = 0u; g_cnt[i] = 0u; }
    if (i == 0) g_rarecnt = 0u;
    if (i < 5) {
        g_pstat[i][0] = 0xFFFFFFFFu; g_pstat[i][1] = 0u;
        g_gstat[i][0] = 0xFFFFFFFFu; g_gstat[i][1] = 0u;
    }
}

// ---------------- fused max+hist ----------------
// tiles per channel: {32,8,2,1,1}; blocks per layer {2048,1024,512,512,512}; total 4608

__device__ __forceinline__ void hist_flush1(unsigned long long h1, int ch) {
#pragma unroll
    for (int j = 0; j < 6; j++) {
        int c1 = (int)((h1 >> (j * 10)) & 1023u);
        c1 = __reduce_add_sync(FULLM, c1);
        if ((threadIdx.x & 31) == 0 && c1) atomicAdd(&g_hist[ch][j], c1);
    }
}

// warp-aggregated append of up to 4 records per lane (msk bits), recs in rec[4]
__device__ __forceinline__ void emit4(unsigned msk, const unsigned* rec, const int* b2, int ch) {
    unsigned any = __ballot_sync(FULLM, msk != 0);
    if (!any) return;
    unsigned lane = threadIdx.x & 31;
    int cnt = __popc(msk);
    int pre = cnt;
#pragma unroll
    for (int o = 1; o < 32; o <<= 1) {
        int t = __shfl_up_sync(FULLM, pre, o);
        if (lane >= o) pre += t;
    }
    int tot = __shfl_sync(FULLM, pre, 31);
    unsigned bs = 0;
    if (lane == 31) bs = atomicAdd(&g_rarecnt, (unsigned)tot);
    bs = __shfl_sync(FULLM, bs, 31);
    unsigned off = bs + (unsigned)(pre - cnt);
#pragma unroll
    for (int k = 0; k < 4; k++) {
        if ((msk >> k) & 1u) {
            g_rare[off++] = rec[k];
            atomicAdd(&g_hist[ch][6 + b2[k]], 1);
        }
    }
}

// shared max-arrive / spin / broadcast; returns channel max
template <int NT>
__device__ __forceinline__ float sync_chmax(float mx, int ch, float* sred, float* smx) {
#pragma unroll
    for (int o = 16; o; o >>= 1) mx = fmaxf(mx, __shfl_xor_sync(FULLM, mx, o));
    if ((threadIdx.x & 31) == 0) sred[threadIdx.x >> 5] = mx;
    __syncthreads();
    if (threadIdx.x == 0) {
        float a = sred[0];
#pragma unroll
        for (int i = 1; i < 8; i++) a = fmaxf(a, sred[i]);
        atomicMax(&g_cmax[ch], __float_as_uint(a));   // nonneg floats: raw-bit monotonic
        if (NT > 1) {
            __threadfence();
            atomicAdd(&g_cnt[ch], 1u);
            while (*(volatile unsigned*)&g_cnt[ch] < (unsigned)NT) __nanosleep(64);
            __threadfence();
        }
        *smx = __uint_as_float(*(volatile unsigned*)&g_cmax[ch]);
    }
    __syncthreads();
    return *smx;
}

template <int H, int T, int NT>
__device__ void fused_v(const float* __restrict__ base, int tile, int ch,
                        float* sred, float* smx) {
    constexpr int W = H, F4 = W / 4;
    int rowsThis = (H - 2 - tile + T - 1) / T;
    int total = rowsThis * F4;
    // -------- phase 1: max (warms L1 with this block's tile) --------
    float mx = 0.f;
#pragma unroll 4
    for (int i = threadIdx.x; i < total; i += THREADS) {
        int m = i / F4, j = i - m * F4;
        int r = 1 + tile + m * T;
        float4 v = *(const float4*)(base + r * W + 4 * j);
        if (j == 0) v.x = 0.f;
        if (j == F4 - 1) v.w = 0.f;
        mx = fmaxf(mx, fmaxf(fmaxf(v.x, v.y), fmaxf(v.z, v.w)));
    }
    float mxc = sync_chmax<NT>(mx, ch, sred, smx);
    // -------- phase 2: hist + rare emission (re-reads same addresses; L1 hits) --------
    float s = (mxc > 0.f) ? __fdiv_rn(1536.f, mxc) : 0.f;
    unsigned long long h1 = 0ULL;
    int iters = (total + THREADS - 1) / THREADS;
    for (int it = 0; it < iters; it++) {
        int i = it * THREADS + threadIdx.x;
        bool ok = i < total;
        int ii = ok ? i : 0;
        int m = ii / F4, j = ii - m * F4;
        int r = 1 + tile + m * T;
        float4 v = ok ? *(const float4*)(base + r * W + 4 * j)
                      : make_float4(1e30f, 1e30f, 1e30f, 1e30f);
        if (ok) {
            if (j == 0) v.x = 0.f;
            if (j == F4 - 1) v.w = 0.f;
        }
        int i1[4];
        i1[0] = __float2int_rd(__fmul_rn(v.x, s));
        i1[1] = __float2int_rd(__fmul_rn(v.y, s));
        i1[2] = __float2int_rd(__fmul_rn(v.z, s));
        i1[3] = __float2int_rd(__fmul_rn(v.w, s));
        if (ok) {
#pragma unroll
            for (int k = 0; k < 4; k++) h1 += 1ULL << (min(i1[k] >> 8, 5) * 10);
        }
        unsigned pix = (unsigned)(r * W + 4 * j);
        unsigned msk = 0;
        unsigned rec[4]; int b2a[4];
        if (ok) {
#pragma unroll
            for (int k = 0; k < 4; k++) {
                bool rr = (i1[k] < 6);
                if (k == 0) rr = rr && (j != 0);          // border col 0: analytic
                if (k == 3) rr = rr && (j != F4 - 1);     // border col W-1: analytic
                int b2 = max(i1[k] - 1, 0);
                b2a[k] = b2;
                rec[k] = (pix + k) | ((unsigned)ch << 18) | ((unsigned)b2 << 29);
                if (rr) msk |= 1u << k;
            }
        }
        emit4(msk, rec, b2a, ch);
    }
    hist_flush1(h1, ch);
    if (tile == 0 && threadIdx.x == 0) {
        atomicAdd(&g_hist[ch][0], 2 * W);                 // rows 0,H-1 -> histc bin 0
        atomicAdd(&g_hist[ch][6 + 0], 2 * (H + W) - 4);   // full border -> gidx bin 0
    }
}

template <int H>
__device__ void fused_s(const float* __restrict__ base, int ch, float* sred, float* smx) {
    constexpr int W = H, IW = W - 2, NI = IW * (H - 2);
    float mx = 0.f;
    for (int i = threadIdx.x; i < NI; i += THREADS) {
        int q = i / IW, col = i - q * IW;
        mx = fmaxf(mx, base[(q + 1) * W + col + 1]);
    }
    float mxc = sync_chmax<1>(mx, ch, sred, smx);
    float s = (mxc > 0.f) ? __fdiv_rn(1536.f, mxc) : 0.f;
    unsigned long long h1 = 0ULL;
    int iters = (NI + THREADS - 1) / THREADS;
    for (int it = 0; it < iters; it++) {
        int i = it * THREADS + threadIdx.x;
        bool ok = i < NI;
        int ii = ok ? i : 0;
        int q = ii / IW, col = ii - q * IW;
        int pix = (q + 1) * W + col + 1;
        float v = ok ? base[pix] : 1e30f;
        int i1 = __float2int_rd(__fmul_rn(v, s));
        if (ok) h1 += 1ULL << (min(i1 >> 8, 5) * 10);
        unsigned msk = (ok && i1 < 6) ? 1u : 0u;
        int b2 = max(i1 - 1, 0);
        unsigned rec[4]; int b2a[4];
        rec[0] = (unsigned)pix | ((unsigned)ch << 18) | ((unsigned)b2 << 29);
        b2a[0] = b2;
        rec[1] = rec[2] = rec[3] = 0; b2a[1] = b2a[2] = b2a[3] = 0;
        emit4(msk, rec, b2a, ch);
    }
    hist_flush1(h1, ch);
    if (threadIdx.x == 0) {
        int Nb = 2 * (H + W) - 4;
        atomicAdd(&g_hist[ch][0], Nb);
        atomicAdd(&g_hist[ch][6 + 0], Nb);
    }
}

__global__ void __launch_bounds__(THREADS) k_maxhist(const float* __restrict__ p0, const float* __restrict__ p1,
                                                     const float* __restrict__ p2, const float* __restrict__ p3,
                                                     const float* __restrict__ p4) {
    __shared__ float sred[8];
    __shared__ float smx;
    int b = blockIdx.x;
    if (b < 2048) {
        int cloc = b >> 5, tile = b & 31;
        fused_v<480, 32, 32>(p0 + (long long)cloc * 230400, tile, cloc, sred, &smx);
    } else if (b < 3072) {
        int t = b - 2048, cloc = t >> 3, tile = t & 7;
        fused_v<240, 8, 8>(p1 + (long long)cloc * 57600, tile, 64 + cloc, sred, &smx);
    } else if (b < 3584) {
        int t = b - 3072, cloc = t >> 1, tile = t & 1;
        fused_v<120, 2, 2>(p2 + (long long)cloc * 14400, tile, 192 + cloc, sred, &smx);
    } else if (b < 4096) {
        int cloc = b - 3584;
        fused_v<60, 1, 1>(p3 + (long long)cloc * 3600, 0, 448 + cloc, sred, &smx);
    } else {
        int cloc = b - 4096;
        fused_s<30>(p4 + (long long)cloc * 900, 960 + cloc, sred, &smx);
    }
}

// ---------------- pass LUT+S5: per-channel LUT, then per-layer S5/bord ----------------
__global__ void __launch_bounds__(THREADS) k_lut_s5() {
    __shared__ float sh[THREADS];
    __shared__ float sbord;
    int l = blockIdx.x;
    int C = c_C[l], cb = c_chanBase[l];
    int H = c_H[l], W = H, HW = H * W;
    float Nf = (float)HW;
    float s5part = 0.f;
    for (int c = threadIdx.x; c < C; c += THREADS) {
        int ch = cb + c;
        int gg[6], sg = 0;
#pragma unroll
        for (int j = 0; j < 5; j++) { gg[j] = g_hist[ch][6 + j]; sg += gg[j]; }
        gg[5] = HW - sg;                      // all non-rare interior pixels have gidx 5

        float hv[6];
#pragma unroll
        for (int j = 0; j < 6; j++)
            hv[j] = -logf(__fdiv_rn((float)g_hist[ch][j], Nf) + 1e-4f);

        float minv = 1e30f, maxv = -1e30f;
#pragma unroll
        for (int j = 0; j < 6; j++)
            if (gg[j] > 0) { minv = fminf(minv, hv[j]); maxv = fmaxf(maxv, hv[j]); }
        float rh = maxv - minv;

        const int jb = 0;                      // border pixels (value 0) -> gidx bin 0
        bool first = (c == 0);                 // channel 0 keeps its border in the map

        float lut[6] = {0.f, 0.f, 0.f, 0.f, 0.f, 0.f};
        if (rh > 0.f) {
            float dn[6];
#pragma unroll
            for (int j = 0; j < 6; j++)
                dn[j] = (gg[j] > 0) ? __fdiv_rn(hv[j] - minv, rh) : 0.f;
            float meandn = 0.f;
#pragma unroll
            for (int j = 0; j < 6; j++) meandn += (float)gg[j] * dn[j];
            meandn = __fdiv_rn(meandn, Nf);
            float w1 = 1.f - meandn; w1 *= w1;     // (max_dst - mean_dst)^2
            int Nb = 2 * (H + W) - 4;
            float mean_m = 0.f;
            float max_m = first ? -1e30f : 0.f;    // zeroed border contributes 0 for c>=1
#pragma unroll
            for (int j = 0; j < 6; j++) {
                int cnt = gg[j] - ((!first && j == jb) ? Nb : 0);
                float rv = dn[j] * w1;
                if (cnt > 0) { mean_m += (float)cnt * rv; max_m = fmaxf(max_m, rv); }
            }
            mean_m = __fdiv_rn(mean_m, Nf);
            if (max_m > 0.f) {
                float w2 = max_m - mean_m; w2 *= w2;   // min_m == 0 always
#pragma unroll
                for (int j = 0; j < 6; j++)
                    lut[j] = __fmul_rn(__fdiv_rn(dn[j] * w1, max_m), w2);
            }
        }
#pragma unroll
        for (int j = 0; j < 6; j++) g_lut[ch][j] = lut[j];
        s5part += lut[5];
        if (c == 0) sbord = lut[jb];
    }
    sh[threadIdx.x] = s5part;
    __syncthreads();
    for (int st = THREADS / 2; st; st >>= 1) {
        if (threadIdx.x < st) sh[threadIdx.x] += sh[threadIdx.x + st];
        __syncthreads();
    }
    if (threadIdx.x == 0) { g_S5[l] = sh[0]; g_bord[l] = sbord; }
}

// ---------------- pass fill: proc = S5 interior, bord on borders ----------------
__global__ void __launch_bounds__(THREADS) k_fill() {
    int i = blockIdx.x * THREADS + threadIdx.x;
    if (i >= 306900) return;
    int layer = i < 230400 ? 0 : i < 288000 ? 1 : i < 302400 ? 2 : i < 306000 ? 3 : 4;
    int W = c_H[layer];
    int p = i - c_procBase[layer];
    int r = p / W, c = p - r * W;
    bool bd = (r == 0) | (c == 0) | (r == W - 1) | (c == W - 1);
    g_proc[i] = bd ? g_bord[layer] : g_S5[layer];
}

// ---------------- pass scatter: apply rare corrections ----------------
__global__ void __launch_bounds__(THREADS) k_scatter() {
    unsigned n = g_rarecnt;
    for (unsigned i = blockIdx.x * THREADS + threadIdx.x; i < n; i += gridDim.x * THREADS) {
        unsigned e = g_rare[i];
        unsigned pix = e & 0x3FFFFu;
        unsigned ch  = (e >> 18) & 0x7FFu;
        unsigned b2  = e >> 29;
        int layer = ch < 64 ? 0 : ch < 192 ? 1 : ch < 448 ? 2 : ch < 960 ? 3 : 4;
        float d = g_lut[ch][b2] - g_lut[ch][5];
        atomicAdd(&g_proc[c_procBase[layer] + pix], d);
    }
}

// ---------------- pass pstat: per-layer proc min/max ----------------
__global__ void __launch_bounds__(THREADS) k_pstat() {
    __shared__ float sred[16];
    int b = blockIdx.x;
    int layer, loc;
    if (b < 900)       { layer = 0; loc = b; }
    else if (b < 1125) { layer = 1; loc = b - 900; }
    else if (b < 1182) { layer = 2; loc = b - 1125; }
    else if (b < 1197) { layer = 3; loc = b - 1182; }
    else               { layer = 4; loc = b - 1197; }
    int H = c_H[layer], HW = H * H, pb = c_procBase[layer];
    int p = loc * THREADS + threadIdx.x;
    float val = g_proc[pb + ((p < HW) ? p : 0)];
    blockMinMax(val, val, g_pstat[layer], sred);
}

// ---------------- pass E: normalize+threshold (fused) + resize + group min/max ----
__device__ __forceinline__ float fth(float v, float mnp, float rng) {
    float pn = (rng == 0.f) ? 0.f : __fdiv_rn(v - mnp, rng);
    return (pn < 0.2f) ? 0.f : pn;
}

__global__ void __launch_bounds__(THREADS) k_resize() {
    __shared__ float sred[16];
    int b = blockIdx.x;
    int layer = b / 225;
    int p = (b - layer * 225) * THREADS + threadIdx.x;   // < 57600 exactly
    int y = p / 240, x = p % 240;
    float mnp = fdec(g_pstat[layer][0]);
    float mxp = fdec(g_pstat[layer][1]);
    float rng = mxp - mnp;
    float val;
    if (layer == 0) {
        // 480 -> 240 antialiased: taps [1,3,3,1]/8, edge-renormalized
        const float w4[4] = {1.f, 3.f, 3.f, 1.f};
        float wxs = 0.f;
#pragma unroll
        for (int j = 0; j < 4; j++) { int tx = 2 * x - 1 + j; if (tx >= 0 && tx < 480) wxs += w4[j]; }
        float acc = 0.f, wys = 0.f;
#pragma unroll
        for (int a = 0; a < 4; a++) {
            int ty = 2 * y - 1 + a;
            if (ty < 0 || ty > 479) continue;
            wys += w4[a];
            const float* row = g_proc + ty * 480;
            float ra = 0.f;
#pragma unroll
            for (int j = 0; j < 4; j++) {
                int tx = 2 * x - 1 + j;
                if (tx >= 0 && tx < 480) ra += w4[j] * fth(row[tx], mnp, rng);
            }
            acc += w4[a] * ra;
        }
        val = acc / (wys * wxs);
    } else if (layer == 1) {
        val = fth(g_proc[230400 + p], mnp, rng);         // identity resize
    } else {
        int H = layer == 2 ? 120 : layer == 3 ? 60 : 30;
        int base = layer == 2 ? 288000 : layer == 3 ? 302400 : 306000;
        const float* pr = g_proc + base;
        float s = (float)H / 240.f;                      // 0.5 / 0.25 / 0.125 exact
        float cy = (y + 0.5f) * s - 0.5f;
        float cx = (x + 0.5f) * s - 0.5f;
        float fly = floorf(cy), flx = floorf(cx);
        float fy = cy - fly, fx = cx - flx;
        int iy = (int)fly, ix = (int)flx;
        int y0 = max(iy, 0), y1 = min(iy + 1, H - 1);
        int x0 = max(ix, 0), x1 = min(ix + 1, H - 1);
        float a = fth(pr[y0 * H + x0], mnp, rng), bv = fth(pr[y0 * H + x1], mnp, rng);
        float c = fth(pr[y1 * H + x0], mnp, rng), d = fth(pr[y1 * H + x1], mnp, rng);
        val = (1.f - fy) * ((1.f - fx) * a + fx * bv) + fy * ((1.f - fx) * c + fx * d);
    }
    g_group[layer][p] = val;
    blockMinMax(val, val, g_gstat[layer], sred);
}

// ---------------- pass F: group normalize(0,256), write groups + sum ----------------
__global__ void __launch_bounds__(THREADS) k_final(float* __restrict__ out, int out_size) {
    int p = blockIdx.x * THREADS + threadIdx.x;          // 225 blocks * 256 = 57600 exactly
    float s = 0.f;
#pragma unroll
    for (int g = 0; g < 5; g++) {
        float mn = fdec(g_gstat[g][0]);
        float mx = fdec(g_gstat[g][1]);
        float rng = mx - mn;
        float v = g_group[g][p];
        float gv = (rng == 0.f) ? 0.f : __fmul_rn(__fdiv_rn(v - mn, rng), 256.f);
        if (out_size >= 345600) out[57600 + p * 5 + g] = gv;
        s += gv;
    }
    out[p] = s;
}

// ---------------- launch ----------------
extern "C" void kernel_launch(void* const* d_in, const int* in_sizes, int n_in,
                              void* d_out, int out_size) {
    const int want[5] = {14745600, 7372800, 3686400, 1843200, 460800};
    const float* L[5] = {nullptr, nullptr, nullptr, nullptr, nullptr};
    for (int i = 0; i < n_in && i < 16; i++)
        for (int j = 0; j < 5; j++)
            if (in_sizes[i] == want[j] && L[j] == nullptr) { L[j] = (const float*)d_in[i]; break; }
    for (int j = 0; j < 5; j++) if (!L[j] && j < n_in) L[j] = (const float*)d_in[j];

    k_init<<<69, THREADS>>>();
    k_maxhist<<<4608, THREADS>>>(L[0], L[1], L[2], L[3], L[4]);
    k_lut_s5<<<5, THREADS>>>();
    k_fill<<<1199, THREADS>>>();
    k_scatter<<<128, THREADS>>>();
    k_pstat<<<1201, THREADS>>>();
    k_resize<<<1125, THREADS>>>();
    k_final<<<225, THREADS>>>((float*)d_out, out_size);
}